// round 11
// baseline (speedup 1.0000x reference)
#include <cuda_runtime.h>
#include <cstdint>

#define GROUPS 4
#define KCODES 1024
#define DIM 64
#define TOK 128
#define TK 128                  // codes per tile
#define HALFK 512               // codes per block
#define NT (HALFK / TK)         // 4 tiles per block

typedef unsigned long long u64t;

__device__ double g_loss_acc;
__device__ float  g_csq[GROUPS * KCODES];
__device__ u64t   g_part[GROUPS * 32768];            // per (g,token) min key
// pre-transposed codebook: [g][tile 0..7][d][128 codes] f32
__device__ __align__(16) float g_ct[GROUPS * 8 * DIM * TK];

__device__ __forceinline__ u64t pack2(float a, float b) {
    u64t r; asm("mov.b64 %0, {%1, %2};" : "=l"(r) : "f"(a), "f"(b)); return r;
}
__device__ __forceinline__ void unpack2(u64t p, float& a, float& b) {
    asm("mov.b64 {%0, %1}, %2;" : "=f"(a), "=f"(b) : "l"(p));
}
__device__ __forceinline__ u64t fma2(u64t a, u64t b, u64t c) {
    u64t d; asm("fma.rn.f32x2 %0, %1, %2, %3;" : "=l"(d) : "l"(a), "l"(b), "l"(c)); return d;
}
__device__ __forceinline__ u64t add2(u64t a, u64t b) {
    u64t d; asm("add.rn.f32x2 %0, %1, %2;" : "=l"(d) : "l"(a), "l"(b)); return d;
}

// ---- prep: loss=0, part keys=MAX, exact csq, transpose codebook ----
__global__ void vq_prep_kernel(const float* __restrict__ cb) {
    int idx = blockIdx.x * blockDim.x + threadIdx.x;   // 65536 threads
    if (idx == 0) g_loss_acc = 0.0;
    g_part[idx] = ~0ull;
    g_part[idx + 65536] = ~0ull;
    if (idx < GROUPS * KCODES) {
        const float4* p = (const float4*)(cb + (size_t)idx * DIM);
        float s = 0.f;
#pragma unroll
        for (int i = 0; i < DIM / 4; i++) {
            float4 v = p[i];
            s = __fadd_rn(s, __fmul_rn(v.x, v.x));
            s = __fadd_rn(s, __fmul_rn(v.y, v.y));
            s = __fadd_rn(s, __fmul_rn(v.z, v.z));
            s = __fadd_rn(s, __fmul_rn(v.w, v.w));
        }
        g_csq[idx] = s;
    }
    {   // transpose: one thread per (g, tile, d, 4-code chunk)
        int kc = idx & 31;
        int d  = (idx >> 5) & 63;
        int tl = (idx >> 11) & 7;
        int g  = idx >> 14;
        float4 o;
        o.x = cb[((size_t)g * KCODES + tl * TK + 4 * kc + 0) * DIM + d];
        o.y = cb[((size_t)g * KCODES + tl * TK + 4 * kc + 1) * DIM + d];
        o.z = cb[((size_t)g * KCODES + tl * TK + 4 * kc + 2) * DIM + d];
        o.w = cb[((size_t)g * KCODES + tl * TK + 4 * kc + 3) * DIM + d];
        *(float4*)(g_ct + ((size_t)(g * 8 + tl) * DIM + d) * TK + 4 * kc) = o;
    }
}

// ---- smem layout (bytes) ----
#define XROW   544              // 128 tok * 4B + 32B pad
#define SM_X   0                // 64 rows x 544 = 34816
#define SM_C   34816            // [64 d][128 k] f32 = 32768
#define SM_CSQ 67584            // 512 f (this half)
#define SM_XSQ 69632            // 128 f
#define SMEM_BYTES 70208

// grid: b = tokblk*8 + half*4 + g
__global__ void __launch_bounds__(256, 2)
vq_main_kernel(const float* __restrict__ lat, int ntok) {
    extern __shared__ char smem[];
    const int tid = threadIdx.x;
    const int ti  = tid & 31;          // tokens 4ti..4ti+3
    const int ci  = tid >> 5;          // codes 16ci..16ci+15 per tile (warp-uniform)
    const int b   = blockIdx.x;
    const int g   = b & 3;
    const int half = (b >> 2) & 1;
    const int tok0 = (b >> 3) * TOK;

    const float* latg = lat + (size_t)g * DIM;
    float* csq_s = (float*)(smem + SM_CSQ);
    float* xsq_s = (float*)(smem + SM_XSQ);

    // ---- stage x: [d][tok] rows, XROW stride
    {
        const int q  = tid & 15;
        const int tb = tid >> 4;
#pragma unroll
        for (int it = 0; it < 8; it++) {
            int t = tb + 16 * it;
            int tok = tok0 + t; if (tok >= ntok) tok = ntok - 1;
            float4 v = *(const float4*)(latg + (size_t)tok * (GROUPS * DIM) + 4 * q);
            float vv[4] = {v.x, v.y, v.z, v.w};
#pragma unroll
            for (int j = 0; j < 4; j++)
                *(float*)(smem + SM_X + (4 * q + j) * XROW + t * 4) = vv[j];
        }
    }
    // ---- xsq: exact reference rounding
    if (tid < TOK) {
        int tok = tok0 + tid; if (tok >= ntok) tok = ntok - 1;
        const float4* xg = (const float4*)(latg + (size_t)tok * (GROUPS * DIM));
        float s = 0.f;
#pragma unroll
        for (int i = 0; i < DIM / 4; i++) {
            float4 v = xg[i];
            s = __fadd_rn(s, __fmul_rn(v.x, v.x));
            s = __fadd_rn(s, __fmul_rn(v.y, v.y));
            s = __fadd_rn(s, __fmul_rn(v.z, v.z));
            s = __fadd_rn(s, __fmul_rn(v.w, v.w));
        }
        xsq_s[tid] = s;
    }
    // ---- csq for this half (512 entries)
    csq_s[tid]       = g_csq[g * KCODES + half * HALFK + tid];
    csq_s[tid + 256] = g_csq[g * KCODES + half * HALFK + tid + 256];

    __syncthreads();           // x + xsq + csq staged

    u64t xsqd[4];
#pragma unroll
    for (int tt = 0; tt < 4; tt++) {
        float v = xsq_s[4 * ti + tt];
        xsqd[tt] = pack2(v, v);
    }
    const u64t NEG2 = pack2(-2.f, -2.f);
    float best[4] = {3.4e38f, 3.4e38f, 3.4e38f, 3.4e38f};
    int   bidx[4] = {0, 0, 0, 0};

    const char* xb = smem + SM_X + ti * 16;
    const char* cbse = smem + SM_C + ci * 64;

    for (int t = 0; t < NT; t++) {
        // ---- copy tile (linear, conflict-free: lane-consecutive 16B)
        {
            const float4* src = (const float4*)(g_ct +
                (size_t)(g * 8 + half * NT + t) * DIM * TK);
            float4* dst = (float4*)(smem + SM_C);
#pragma unroll
            for (int i = 0; i < 8; i++)
                dst[i * 256 + tid] = src[i * 256 + tid];
        }
        __syncthreads();       // tile visible

        // ---- compute: software-pipelined x load; tt-outer/p-inner FFMA2
        //      (8 consecutive FFMA2 share xd in one operand slot -> .reuse)
        u64t acc[4][8];
#pragma unroll
        for (int tt = 0; tt < 4; tt++)
#pragma unroll
            for (int p = 0; p < 8; p++) acc[tt][p] = 0ull;

        float4 xv = *(const float4*)(xb);
#pragma unroll 8
        for (int d = 0; d < DIM; d++) {
            // prefetch next-d x (d=63 reads into c-region: in-bounds, unused)
            float4 xn = *(const float4*)(xb + (d + 1) * XROW);
            ulonglong2 cA = *(const ulonglong2*)(cbse + d * 512);
            ulonglong2 cB = *(const ulonglong2*)(cbse + d * 512 + 16);
            ulonglong2 cC = *(const ulonglong2*)(cbse + d * 512 + 32);
            ulonglong2 cD = *(const ulonglong2*)(cbse + d * 512 + 48);
            u64t xd0 = pack2(xv.x, xv.x);
            u64t xd1 = pack2(xv.y, xv.y);
            u64t xd2 = pack2(xv.z, xv.z);
            u64t xd3 = pack2(xv.w, xv.w);
            acc[0][0] = fma2(xd0, cA.x, acc[0][0]);
            acc[0][1] = fma2(xd0, cA.y, acc[0][1]);
            acc[0][2] = fma2(xd0, cB.x, acc[0][2]);
            acc[0][3] = fma2(xd0, cB.y, acc[0][3]);
            acc[0][4] = fma2(xd0, cC.x, acc[0][4]);
            acc[0][5] = fma2(xd0, cC.y, acc[0][5]);
            acc[0][6] = fma2(xd0, cD.x, acc[0][6]);
            acc[0][7] = fma2(xd0, cD.y, acc[0][7]);
            acc[1][0] = fma2(xd1, cA.x, acc[1][0]);
            acc[1][1] = fma2(xd1, cA.y, acc[1][1]);
            acc[1][2] = fma2(xd1, cB.x, acc[1][2]);
            acc[1][3] = fma2(xd1, cB.y, acc[1][3]);
            acc[1][4] = fma2(xd1, cC.x, acc[1][4]);
            acc[1][5] = fma2(xd1, cC.y, acc[1][5]);
            acc[1][6] = fma2(xd1, cD.x, acc[1][6]);
            acc[1][7] = fma2(xd1, cD.y, acc[1][7]);
            acc[2][0] = fma2(xd2, cA.x, acc[2][0]);
            acc[2][1] = fma2(xd2, cA.y, acc[2][1]);
            acc[2][2] = fma2(xd2, cB.x, acc[2][2]);
            acc[2][3] = fma2(xd2, cB.y, acc[2][3]);
            acc[2][4] = fma2(xd2, cC.x, acc[2][4]);
            acc[2][5] = fma2(xd2, cC.y, acc[2][5]);
            acc[2][6] = fma2(xd2, cD.x, acc[2][6]);
            acc[2][7] = fma2(xd2, cD.y, acc[2][7]);
            acc[3][0] = fma2(xd3, cA.x, acc[3][0]);
            acc[3][1] = fma2(xd3, cA.y, acc[3][1]);
            acc[3][2] = fma2(xd3, cB.x, acc[3][2]);
            acc[3][3] = fma2(xd3, cB.y, acc[3][3]);
            acc[3][4] = fma2(xd3, cC.x, acc[3][4]);
            acc[3][5] = fma2(xd3, cC.y, acc[3][5]);
            acc[3][6] = fma2(xd3, cD.x, acc[3][6]);
            acc[3][7] = fma2(xd3, cD.y, acc[3][7]);
            xv = xn;
        }

        // ---- scan: dist = round(xsq - 2*dot) + csq  (exact ref sequence)
        const u64t* csq2 = (const u64t*)csq_s;
#pragma unroll
        for (int p = 0; p < 8; p++) {
            u64t cs = csq2[(t * TK + 16 * ci) / 2 + p];
            int kidx = half * HALFK + t * TK + 16 * ci + 2 * p;
#pragma unroll
            for (int tt = 0; tt < 4; tt++) {
                u64t pk = fma2(acc[tt][p], NEG2, xsqd[tt]);
                pk = add2(pk, cs);
                float d0, d1; unpack2(pk, d0, d1);
                if (d0 < best[tt]) { best[tt] = d0; bidx[tt] = kidx; }
                if (d1 < best[tt]) { best[tt] = d1; bidx[tt] = kidx + 1; }
            }
        }
        __syncthreads();       // scan done before next tile copy overwrites
    }

    // ---- one atomicMin per (token, half): key = dist_bits<<32 | k
#pragma unroll
    for (int tt = 0; tt < 4; tt++) {
        int tok = tok0 + 4 * ti + tt;
        if (tok < ntok) {
            u64t key = ((u64t)__float_as_uint(best[tt]) << 32) | (unsigned)bidx[tt];
            atomicMin(&g_part[(size_t)g * 32768 + tok], key);
        }
    }
}

// ---- finalize: gather winners, out = x + (q-x), loss ----
__global__ void vq_final_kernel(const float* __restrict__ lat,
                                const float* __restrict__ cb,
                                float* __restrict__ out, int ntok) {
    __shared__ double sred[8];
    int idx = blockIdx.x * blockDim.x + threadIdx.x;
    int gtok = idx >> 2;
    int part = idx & 3;
    int g   = gtok >> 15;
    int tok = gtok & 32767;
    float lsum = 0.f;
    if (tok < ntok) {
        int k = (int)(g_part[gtok] & 1023u);
        const float4* cq = (const float4*)(cb + ((size_t)g * KCODES + k) * DIM + part * 16);
        const float4* xg = (const float4*)(lat + (size_t)tok * (GROUPS * DIM) + g * DIM + part * 16);
        float4* og = (float4*)(out + (size_t)tok * (GROUPS * DIM) + g * DIM + part * 16);
#pragma unroll
        for (int i = 0; i < 4; i++) {
            float4 xv = xg[i];
            float4 cv = cq[i];
            float4 o; float t2;
            t2 = __fsub_rn(cv.x, xv.x); o.x = __fadd_rn(xv.x, t2); lsum = __fmaf_rn(t2, t2, lsum);
            t2 = __fsub_rn(cv.y, xv.y); o.y = __fadd_rn(xv.y, t2); lsum = __fmaf_rn(t2, t2, lsum);
            t2 = __fsub_rn(cv.z, xv.z); o.z = __fadd_rn(xv.z, t2); lsum = __fmaf_rn(t2, t2, lsum);
            t2 = __fsub_rn(cv.w, xv.w); o.w = __fadd_rn(xv.w, t2); lsum = __fmaf_rn(t2, t2, lsum);
            og[i] = o;
        }
    }
#pragma unroll
    for (int off = 16; off; off >>= 1)
        lsum += __shfl_xor_sync(0xFFFFFFFFu, lsum, off);
    if ((threadIdx.x & 31) == 0) sred[threadIdx.x >> 5] = (double)lsum;
    __syncthreads();
    if (threadIdx.x == 0) {
        double acc = 0.0;
#pragma unroll
        for (int i = 0; i < 8; i++) acc += sred[i];
        atomicAdd(&g_loss_acc, acc);
    }
}

__global__ void vq_finish_kernel(float* __restrict__ out, long long loss_idx,
                                 long long count) {
    double m = g_loss_acc / (double)count;
    float mf = (float)m;
    out[loss_idx] = __fadd_rn(__fmul_rn(mf, 0.25f), mf);
}

extern "C" void kernel_launch(void* const* d_in, const int* in_sizes, int n_in,
                              void* d_out, int out_size) {
    const float* lat = (const float*)d_in[0];
    const float* cb  = (const float*)d_in[1];
    float* out = (float*)d_out;

    const int n_lat = in_sizes[0];
    const int ntok  = n_lat / (GROUPS * DIM);

    cudaFuncSetAttribute(vq_main_kernel,
                         cudaFuncAttributeMaxDynamicSharedMemorySize, SMEM_BYTES);

    vq_prep_kernel<<<256, 256>>>(cb);              // 65536 threads

    int tokBlocks = (ntok + TOK - 1) / TOK;
    vq_main_kernel<<<tokBlocks * GROUPS * 2, 256, SMEM_BYTES>>>(lat, ntok);

    vq_final_kernel<<<(GROUPS * 32768 * 4) / 256, 256>>>(lat, cb, out, ntok);

    vq_finish_kernel<<<1, 1>>>(out, (long long)out_size - 1, (long long)n_lat);
}

// round 12
// speedup vs baseline: 1.8460x; 1.8460x over previous
#include <cuda_runtime.h>
#include <cstdint>

#define GROUPS 4
#define KCODES 1024
#define DIM 64
#define TOK 128
#define TK 128                  // codes per tile
#define NT (KCODES / TK)        // 8 tiles (full K per block)

typedef unsigned long long u64t;

__device__ double g_loss_acc;
__device__ float  g_csq[GROUPS * KCODES];
// pre-transposed codebook: [g][tile 0..7][d][128 codes] f32
__device__ __align__(16) float g_ct[GROUPS * 8 * DIM * TK];

__device__ __forceinline__ u64t pack2(float a, float b) {
    u64t r; asm("mov.b64 %0, {%1, %2};" : "=l"(r) : "f"(a), "f"(b)); return r;
}
__device__ __forceinline__ void unpack2(u64t p, float& a, float& b) {
    asm("mov.b64 {%0, %1}, %2;" : "=f"(a), "=f"(b) : "l"(p));
}
__device__ __forceinline__ u64t fma2(u64t a, u64t b, u64t c) {
    u64t d; asm("fma.rn.f32x2 %0, %1, %2, %3;" : "=l"(d) : "l"(a), "l"(b), "l"(c)); return d;
}
__device__ __forceinline__ u64t add2(u64t a, u64t b) {
    u64t d; asm("add.rn.f32x2 %0, %1, %2;" : "=l"(d) : "l"(a), "l"(b)); return d;
}

// ---- prep: loss=0, exact csq, transpose codebook ----
__global__ void vq_prep_kernel(const float* __restrict__ cb) {
    int idx = blockIdx.x * blockDim.x + threadIdx.x;   // 65536 threads
    if (idx == 0) g_loss_acc = 0.0;
    if (idx < GROUPS * KCODES) {
        const float4* p = (const float4*)(cb + (size_t)idx * DIM);
        float s = 0.f;
#pragma unroll
        for (int i = 0; i < DIM / 4; i++) {
            float4 v = p[i];
            s = __fadd_rn(s, __fmul_rn(v.x, v.x));
            s = __fadd_rn(s, __fmul_rn(v.y, v.y));
            s = __fadd_rn(s, __fmul_rn(v.z, v.z));
            s = __fadd_rn(s, __fmul_rn(v.w, v.w));
        }
        g_csq[idx] = s;
    }
    {   // transpose: one thread per (g, tile, d, 4-code chunk)
        int kc = idx & 31;
        int d  = (idx >> 5) & 63;
        int tl = (idx >> 11) & 7;
        int g  = idx >> 14;
        float4 o;
        o.x = cb[((size_t)g * KCODES + tl * TK + 4 * kc + 0) * DIM + d];
        o.y = cb[((size_t)g * KCODES + tl * TK + 4 * kc + 1) * DIM + d];
        o.z = cb[((size_t)g * KCODES + tl * TK + 4 * kc + 2) * DIM + d];
        o.w = cb[((size_t)g * KCODES + tl * TK + 4 * kc + 3) * DIM + d];
        *(float4*)(g_ct + ((size_t)(g * 8 + tl) * DIM + d) * TK + 4 * kc) = o;
    }
}

// ---- smem layout (bytes) ----
#define XROW   544              // 128 tok * 4B + 32B pad
#define SM_X   0                // 64 rows x 544 = 34816
#define SM_C   34816            // [64 d][128 k] f32 = 32768
#define SM_CSQ 67584            // 1024 f (full K)
#define SM_XSQ 71680            // 128 f
#define SM_SRED 72192           // 8 dbl
#define SMEM_BYTES 72256
// reduction arrays reuse the C buffer after the final sync:
#define SM_RD  34816            // 128*8 f
#define SM_RI  38912            // 128*8 int

// grid: b = tokblk*4 + g
__global__ void __launch_bounds__(256, 2)
vq_main_kernel(const float* __restrict__ lat, const float* __restrict__ cb,
               float* __restrict__ out, int ntok) {
    extern __shared__ char smem[];
    const int tid = threadIdx.x;
    const int ti  = tid & 31;          // tokens 4ti..4ti+3
    const int ci  = tid >> 5;          // codes 16ci..16ci+15 per tile (warp-uniform)
    const int b   = blockIdx.x;
    const int g   = b & 3;
    const int tok0 = (b >> 2) * TOK;

    const float* latg = lat + (size_t)g * DIM;
    const float* cbg  = cb + (size_t)g * KCODES * DIM;
    float* csq_s = (float*)(smem + SM_CSQ);
    float* xsq_s = (float*)(smem + SM_XSQ);

    // ---- stage x: [d][tok] rows, XROW stride (R7-proven)
    {
        const int q  = tid & 15;
        const int tb = tid >> 4;
#pragma unroll
        for (int it = 0; it < 8; it++) {
            int t = tb + 16 * it;
            int tok = tok0 + t; if (tok >= ntok) tok = ntok - 1;
            float4 v = *(const float4*)(latg + (size_t)tok * (GROUPS * DIM) + 4 * q);
            float vv[4] = {v.x, v.y, v.z, v.w};
#pragma unroll
            for (int j = 0; j < 4; j++)
                *(float*)(smem + SM_X + (4 * q + j) * XROW + t * 4) = vv[j];
        }
    }
    // ---- xsq: exact reference rounding
    if (tid < TOK) {
        int tok = tok0 + tid; if (tok >= ntok) tok = ntok - 1;
        const float4* xg = (const float4*)(latg + (size_t)tok * (GROUPS * DIM));
        float s = 0.f;
#pragma unroll
        for (int i = 0; i < DIM / 4; i++) {
            float4 v = xg[i];
            s = __fadd_rn(s, __fmul_rn(v.x, v.x));
            s = __fadd_rn(s, __fmul_rn(v.y, v.y));
            s = __fadd_rn(s, __fmul_rn(v.z, v.z));
            s = __fadd_rn(s, __fmul_rn(v.w, v.w));
        }
        xsq_s[tid] = s;
    }
    // ---- csq (full K)
#pragma unroll
    for (int r = 0; r < 4; r++) csq_s[tid + 256 * r] = g_csq[g * KCODES + tid + 256 * r];

    __syncthreads();           // x + xsq + csq staged

    u64t xsqd[4];
#pragma unroll
    for (int tt = 0; tt < 4; tt++) {
        float v = xsq_s[4 * ti + tt];
        xsqd[tt] = pack2(v, v);
    }
    const u64t NEG2 = pack2(-2.f, -2.f);
    float best[4] = {3.4e38f, 3.4e38f, 3.4e38f, 3.4e38f};
    int   bidx[4] = {0, 0, 0, 0};

    const char* xb = smem + SM_X + ti * 16;
    const char* cbse = smem + SM_C + ci * 64;

    for (int t = 0; t < NT; t++) {
        // ---- copy tile (linear, conflict-free: lane-consecutive 16B)
        {
            const float4* src = (const float4*)(g_ct + (size_t)(g * 8 + t) * DIM * TK);
            float4* dst = (float4*)(smem + SM_C);
#pragma unroll
            for (int i = 0; i < 8; i++)
                dst[i * 256 + tid] = src[i * 256 + tid];
        }
        __syncthreads();       // tile visible

        // ---- compute (R7-proven ordering: p-outer over c, tt-inner)
        u64t acc[4][8];
#pragma unroll
        for (int tt = 0; tt < 4; tt++)
#pragma unroll
            for (int p = 0; p < 8; p++) acc[tt][p] = 0ull;

#pragma unroll 8
        for (int d = 0; d < DIM; d++) {
            float4 xv = *(const float4*)(xb + d * XROW);
            u64t xd0 = pack2(xv.x, xv.x);
            u64t xd1 = pack2(xv.y, xv.y);
            u64t xd2 = pack2(xv.z, xv.z);
            u64t xd3 = pack2(xv.w, xv.w);
            ulonglong2 cA = *(const ulonglong2*)(cbse + d * 512);
            ulonglong2 cB = *(const ulonglong2*)(cbse + d * 512 + 16);
            ulonglong2 cC = *(const ulonglong2*)(cbse + d * 512 + 32);
            ulonglong2 cD = *(const ulonglong2*)(cbse + d * 512 + 48);
            acc[0][0] = fma2(xd0, cA.x, acc[0][0]);
            acc[1][0] = fma2(xd1, cA.x, acc[1][0]);
            acc[2][0] = fma2(xd2, cA.x, acc[2][0]);
            acc[3][0] = fma2(xd3, cA.x, acc[3][0]);
            acc[0][1] = fma2(xd0, cA.y, acc[0][1]);
            acc[1][1] = fma2(xd1, cA.y, acc[1][1]);
            acc[2][1] = fma2(xd2, cA.y, acc[2][1]);
            acc[3][1] = fma2(xd3, cA.y, acc[3][1]);
            acc[0][2] = fma2(xd0, cB.x, acc[0][2]);
            acc[1][2] = fma2(xd1, cB.x, acc[1][2]);
            acc[2][2] = fma2(xd2, cB.x, acc[2][2]);
            acc[3][2] = fma2(xd3, cB.x, acc[3][2]);
            acc[0][3] = fma2(xd0, cB.y, acc[0][3]);
            acc[1][3] = fma2(xd1, cB.y, acc[1][3]);
            acc[2][3] = fma2(xd2, cB.y, acc[2][3]);
            acc[3][3] = fma2(xd3, cB.y, acc[3][3]);
            acc[0][4] = fma2(xd0, cC.x, acc[0][4]);
            acc[1][4] = fma2(xd1, cC.x, acc[1][4]);
            acc[2][4] = fma2(xd2, cC.x, acc[2][4]);
            acc[3][4] = fma2(xd3, cC.x, acc[3][4]);
            acc[0][5] = fma2(xd0, cC.y, acc[0][5]);
            acc[1][5] = fma2(xd1, cC.y, acc[1][5]);
            acc[2][5] = fma2(xd2, cC.y, acc[2][5]);
            acc[3][5] = fma2(xd3, cC.y, acc[3][5]);
            acc[0][6] = fma2(xd0, cD.x, acc[0][6]);
            acc[1][6] = fma2(xd1, cD.x, acc[1][6]);
            acc[2][6] = fma2(xd2, cD.x, acc[2][6]);
            acc[3][6] = fma2(xd3, cD.x, acc[3][6]);
            acc[0][7] = fma2(xd0, cD.y, acc[0][7]);
            acc[1][7] = fma2(xd1, cD.y, acc[1][7]);
            acc[2][7] = fma2(xd2, cD.y, acc[2][7]);
            acc[3][7] = fma2(xd3, cD.y, acc[3][7]);
        }

        // ---- scan: dist = round(xsq - 2*dot) + csq  (exact ref sequence)
        const u64t* csq2 = (const u64t*)csq_s;
#pragma unroll
        for (int p = 0; p < 8; p++) {
            u64t cs = csq2[(t * TK + 16 * ci) / 2 + p];
            int kidx = t * TK + 16 * ci + 2 * p;
#pragma unroll
            for (int tt = 0; tt < 4; tt++) {
                u64t pk = fma2(acc[tt][p], NEG2, xsqd[tt]);
                pk = add2(pk, cs);
                float d0, d1; unpack2(pk, d0, d1);
                if (d0 < best[tt]) { best[tt] = d0; bidx[tt] = kidx; }
                if (d1 < best[tt]) { best[tt] = d1; bidx[tt] = kidx + 1; }
            }
        }
        __syncthreads();       // scan done before next tile copy overwrites
    }

    // ---- block-wide argmin (R2-proven): 8 ci-candidates, (dist, idx) tie-break
    {
        float* red_d = (float*)(smem + SM_RD);
        int*   red_i = (int*)(smem + SM_RI);
#pragma unroll
        for (int tt = 0; tt < 4; tt++) {
            red_d[(4 * ti + tt) * 8 + ci] = best[tt];
            red_i[(4 * ti + tt) * 8 + ci] = bidx[tt];
        }
    }
    __syncthreads();

    float lsum = 0.f;
    if (tid < TOK) {
        const float* red_d = (const float*)(smem + SM_RD);
        const int*   red_i = (const int*)(smem + SM_RI);
        float bv = red_d[tid * 8];
        int   bi = red_i[tid * 8];
#pragma unroll
        for (int c = 1; c < 8; c++) {
            float d = red_d[tid * 8 + c];
            int   i = red_i[tid * 8 + c];
            if (d < bv || (d == bv && i < bi)) { bv = d; bi = i; }
        }
        int tok = tok0 + tid;
        bool valid = (tok < ntok);
        if (!valid) tok = ntok - 1;
        const float4* cq = (const float4*)(cbg + (size_t)bi * DIM);
        const float4* xg = (const float4*)(latg + (size_t)tok * (GROUPS * DIM));
        float4* stage = (float4*)(smem + SM_X);
        if (valid) {
#pragma unroll
            for (int i = 0; i < DIM / 4; i++) {
                int f = (i + tid) & 15;
                float4 xv = xg[f];
                float4 cv = cq[f];
                float4 o; float t2;
                t2 = __fsub_rn(cv.x, xv.x); o.x = __fadd_rn(xv.x, t2); lsum = __fmaf_rn(t2, t2, lsum);
                t2 = __fsub_rn(cv.y, xv.y); o.y = __fadd_rn(xv.y, t2); lsum = __fmaf_rn(t2, t2, lsum);
                t2 = __fsub_rn(cv.z, xv.z); o.z = __fadd_rn(xv.z, t2); lsum = __fmaf_rn(t2, t2, lsum);
                t2 = __fsub_rn(cv.w, xv.w); o.w = __fadd_rn(xv.w, t2); lsum = __fmaf_rn(t2, t2, lsum);
                stage[tid * 16 + f] = o;
            }
        }
    }

#pragma unroll
    for (int off = 16; off; off >>= 1)
        lsum += __shfl_xor_sync(0xFFFFFFFFu, lsum, off);
    if ((tid & 31) == 0) ((double*)(smem + SM_SRED))[tid >> 5] = (double)lsum;
    __syncthreads();
    if (tid == 0) {
        double acc2 = 0.0;
#pragma unroll
        for (int i = 0; i < 8; i++) acc2 += ((const double*)(smem + SM_SRED))[i];
        atomicAdd(&g_loss_acc, acc2);
    }

    // ---- coalesced output store from staging
    {
        const float4* st = (const float4*)(smem + SM_X);
#pragma unroll
        for (int r = 0; r < 8; r++) {
            int li = tid + r * 256;
            int tt = li >> 4, f = li & 15;
            int tok = tok0 + tt;
            if (tok < ntok)
                *(float4*)(out + (size_t)tok * (GROUPS * DIM) + g * DIM + 4 * f) = st[li];
        }
    }
}

__global__ void vq_finish_kernel(float* __restrict__ out, long long loss_idx,
                                 long long count) {
    double m = g_loss_acc / (double)count;
    float mf = (float)m;
    out[loss_idx] = __fadd_rn(__fmul_rn(mf, 0.25f), mf);
}

extern "C" void kernel_launch(void* const* d_in, const int* in_sizes, int n_in,
                              void* d_out, int out_size) {
    const float* lat = (const float*)d_in[0];
    const float* cb  = (const float*)d_in[1];
    float* out = (float*)d_out;

    const int n_lat = in_sizes[0];
    const int ntok  = n_lat / (GROUPS * DIM);

    cudaFuncSetAttribute(vq_main_kernel,
                         cudaFuncAttributeMaxDynamicSharedMemorySize, SMEM_BYTES);

    vq_prep_kernel<<<256, 256>>>(cb);              // 65536 threads

    int tokBlocks = (ntok + TOK - 1) / TOK;
    vq_main_kernel<<<tokBlocks * GROUPS, 256, SMEM_BYTES>>>(lat, cb, out, ntok);

    vq_finish_kernel<<<1, 1>>>(out, (long long)out_size - 1, (long long)n_lat);
}